// round 15
// baseline (speedup 1.0000x reference)
#include <cuda_runtime.h>
#include <cuda_fp16.h>
#include <math.h>

#define L 2048
#define CA 256
#define NH 8
#define HD 32
#define NB 4
static const size_t L2 = (size_t)L * L;

// ---------------- scratch (device globals; no allocation allowed) ----------------
__device__ float g_consts[4];           // c_in, c_skip, c_out, c_noise
__device__ float g_tc[256];
__device__ float g_ss1[NB][512];
__device__ float g_ss2[NB][512];
__device__ float g_h[L * CA];
__device__ float g_h1[L * CA];
__device__ float g_q[L * CA];
__device__ float g_k[L * CA];
__device__ float g_v[L * CA];
__device__ float g_o[L * CA];
__device__ float g_ffn[L * 1024];
__device__ __half g_bias[134217728];    // [NB*NH][L][L] fp16 = 256 MB

__device__ __forceinline__ float* bufsel(int s) {
    switch (s) {
        case 0: return g_h;
        case 1: return g_h1;
        case 2: return g_q;
        case 3: return g_k;
        case 4: return g_v;
        case 5: return g_o;
        case 6: return g_ffn;
    }
    return nullptr;
}

// ---------------- packed f32x2 helpers (FFMA2) ----------------
typedef unsigned long long f32x2;

__device__ __forceinline__ f32x2 pack2(float lo, float hi) {
    f32x2 r;
    asm("mov.b64 %0, {%1, %2};" : "=l"(r) : "f"(lo), "f"(hi));
    return r;
}
__device__ __forceinline__ void unpack2(f32x2 v, float& a, float& b) {
    asm("mov.b64 {%0, %1}, %2;" : "=f"(a), "=f"(b) : "l"(v));
}
__device__ __forceinline__ void fma2(f32x2& d, f32x2 a, f32x2 b) {
    asm("fma.rn.f32x2 %0, %1, %2, %3;" : "=l"(d) : "l"(a), "l"(b), "l"(d));
}
__device__ __forceinline__ void add2(f32x2& d, f32x2 a) {
    asm("add.rn.f32x2 %0, %1, %2;" : "=l"(d) : "l"(a), "l"(d));
}
__device__ __forceinline__ f32x2 f2lo(float4 v) { return pack2(v.x, v.y); }
__device__ __forceinline__ f32x2 f2hi(float4 v) { return pack2(v.z, v.w); }

__device__ __forceinline__ float gelu_exact(float x) {
    return 0.5f * x * (1.0f + erff(x * 0.7071067811865475f));
}

__device__ __forceinline__ unsigned tf32of(float f) {
    unsigned r;
    asm("cvt.rna.tf32.f32 %0, %1;" : "=r"(r) : "f"(f));
    return r;
}

// ---------------- merged setup: consts + time MLP (1 CTA, 1024 threads) ----------------
__global__ void k_setup(const float* __restrict__ sigma,
                        const float* __restrict__ W1, const float* __restrict__ b1,
                        const float* __restrict__ W2, const float* __restrict__ b2) {
    __shared__ float temb[256];
    __shared__ float hid[1024];
    int t = threadIdx.x;
    float s = sigma[0];
    if (t == 0) {
        float s2 = s * s + 256.0f;
        g_consts[0] = rsqrtf(s2);               // c_in
        g_consts[1] = 256.0f / s2;              // c_skip
        g_consts[2] = s * 16.0f * rsqrtf(s2);   // c_out
        g_consts[3] = 0.25f * logf(s + 1e-8f);  // c_noise
    }
    float cn = 0.25f * logf(s + 1e-8f);
    if (t < 256) {
        int j = t & 127;
        float f = expf(-logf(10000.0f) * (float)j / 128.0f);
        float a = cn * f;
        temb[t] = (t < 128) ? cosf(a) : sinf(a);
    }
    __syncthreads();
    {
        const float* w = W1 + (size_t)t * 256;
        float acc = 0.0f;
        #pragma unroll 8
        for (int c = 0; c < 256; c++) acc += temb[c] * w[c];
        hid[t] = gelu_exact(acc + b1[t]);
    }
    __syncthreads();
    if (t < 256) {
        const float* w = W2 + (size_t)t * 1024;
        float acc = 0.0f;
        #pragma unroll 8
        for (int c = 0; c < 1024; c++) acc += hid[c] * w[c];
        g_tc[t] = acc + b2[t];
    }
}

// ada scale/shift: one warp per output row, coalesced weight reads.
__global__ void k_ada(const float* __restrict__ pW1, const float* __restrict__ pb1,
                      const float* __restrict__ pW2, const float* __restrict__ pb2) {
    int wid = threadIdx.x >> 5, lane = threadIdx.x & 31;
    int gid = blockIdx.x * 8 + wid;   // 0..4095
    int blk = gid >> 10;
    int which = (gid >> 9) & 1;
    int idx = gid & 511;
    const float* W = which ? pW2 : pW1;
    const float* pb = which ? pb2 : pb1;
    const float* w = W + ((size_t)blk * 512 + idx) * 256;
    float acc = 0.0f;
    #pragma unroll
    for (int c = lane; c < 256; c += 32) acc += g_tc[c] * w[c];
    #pragma unroll
    for (int off = 16; off > 0; off >>= 1)
        acc += __shfl_xor_sync(0xffffffffu, acc, off);
    if (lane == 0) {
        float val = acc + pb[blk * 512 + idx];
        if (which) g_ss2[blk][idx] = val; else g_ss1[blk][idx] = val;
    }
}

// ---------------- pair bias via tensor cores (tf32 mma.sync) ----------------
__global__ void __launch_bounds__(128) k_pairbias(const float* __restrict__ pair,
                                                  const float* __restrict__ pW) {
    __shared__ __align__(16) char sm[34816 + 8704];  // As | Bs ; Ds aliases As
    unsigned (*As)[68] = (unsigned(*)[68])sm;          // [128][68]
    unsigned (*Bs)[68] = (unsigned(*)[68])(sm + 34816);// [32][68]
    __half   (*Ds)[136] = (__half(*)[136])sm;          // [32][136] aliases As

    size_t r0 = (size_t)blockIdx.x * 128;
    int tid = threadIdx.x, lane = tid & 31, w = tid >> 5;

    const float4* Ap4 = (const float4*)(pair + r0 * 64);
    #pragma unroll
    for (int l = 0; l < 16; l++) {
        int idx = tid + l * 128;
        float4 v = Ap4[idx];
        int r = idx >> 4, c4 = (idx & 15) * 4;
        uint4 t4 = make_uint4(tf32of(v.x), tf32of(v.y), tf32of(v.z), tf32of(v.w));
        *(uint4*)&As[r][c4] = t4;
    }
    #pragma unroll
    for (int l = 0; l < 16; l++) {
        int idx = tid + l * 128;
        Bs[idx >> 6][idx & 63] = tf32of(pW[idx]);
    }
    __syncthreads();

    float acc[2][4][4];
    #pragma unroll
    for (int mt = 0; mt < 2; mt++)
        #pragma unroll
        for (int nt = 0; nt < 4; nt++)
            #pragma unroll
            for (int q = 0; q < 4; q++) acc[mt][nt][q] = 0.0f;

    int qr_ = lane >> 2, qc = lane & 3;
    #pragma unroll
    for (int k = 0; k < 8; k++) {
        int kc = k * 8 + qc;
        unsigned b0[4], b1[4];
        #pragma unroll
        for (int nt = 0; nt < 4; nt++) {
            b0[nt] = Bs[nt * 8 + qr_][kc];
            b1[nt] = Bs[nt * 8 + qr_][kc + 4];
        }
        #pragma unroll
        for (int mt = 0; mt < 2; mt++) {
            int mr = w * 32 + mt * 16 + qr_;
            unsigned a0 = As[mr][kc];
            unsigned a1 = As[mr + 8][kc];
            unsigned a2 = As[mr][kc + 4];
            unsigned a3 = As[mr + 8][kc + 4];
            #pragma unroll
            for (int nt = 0; nt < 4; nt++) {
                asm volatile(
                    "mma.sync.aligned.m16n8k8.row.col.f32.tf32.tf32.f32 "
                    "{%0,%1,%2,%3}, {%4,%5,%6,%7}, {%8,%9}, {%0,%1,%2,%3};"
                    : "+f"(acc[mt][nt][0]), "+f"(acc[mt][nt][1]),
                      "+f"(acc[mt][nt][2]), "+f"(acc[mt][nt][3])
                    : "r"(a0), "r"(a1), "r"(a2), "r"(a3),
                      "r"(b0[nt]), "r"(b1[nt]));
            }
        }
    }
    __syncthreads();

    #pragma unroll
    for (int mt = 0; mt < 2; mt++) {
        int r = w * 32 + mt * 16 + qr_;
        #pragma unroll
        for (int nt = 0; nt < 4; nt++) {
            int n = nt * 8 + qc * 2;
            Ds[n][r]         = __float2half(acc[mt][nt][0]);
            Ds[n + 1][r]     = __float2half(acc[mt][nt][1]);
            Ds[n][r + 8]     = __float2half(acc[mt][nt][2]);
            Ds[n + 1][r + 8] = __float2half(acc[mt][nt][3]);
        }
    }
    __syncthreads();
    #pragma unroll
    for (int l = 0; l < 16; l++) {
        int idx = tid + l * 128;
        int plane = idx >> 6, off = (idx & 63) * 2;
        __half2 hv = __halves2half2(Ds[plane][off], Ds[plane][off + 1]);
        *(__half2*)(g_bias + (size_t)plane * L2 + r0 + off) = hv;
    }
}

// ---------------- generic GEMM: C[M,N] = epi(A[M,K] @ W[N,K]^T) ----------------
// Tile: BM = 32*RP rows x 64 cols, BK=32, 256 threads. Software-pipelined k-loop.
#define EPI_BIAS  1
#define EPI_GELU  2
#define EPI_RES   4
#define EPI_COORD 8

template <int RP, int EPI>
__global__ void __launch_bounds__(256) k_gemm(
                       const float* __restrict__ Aext, int a_sel,
                       const float* __restrict__ Wa, const float* __restrict__ Wb,
                       const float* __restrict__ Wc,
                       const float* __restrict__ bias,
                       int res_sel, int c_sel0, int K, int N,
                       const float* __restrict__ x3,
                       const float* __restrict__ cw3,
                       const float* __restrict__ cb3) {
    const int BM = 32 * RP;
    __shared__ __align__(16) float As[32][BM + 2];
    __shared__ __align__(16) float2 Bs[32][65];   // duplicated (b,b)
    const float* A = (a_sel >= 0) ? bufsel(a_sel) : Aext;
    int z = blockIdx.z;
    const float* W = (z == 0) ? Wa : (z == 1 ? Wb : Wc);
    float* C = bufsel(c_sel0 + z);
    int m0 = blockIdx.y * BM, n0 = blockIdx.x * 64;
    int tid = threadIdx.x, tx = tid & 15, ty = tid >> 4;

    f32x2 acc2[RP][4];
    #pragma unroll
    for (int i = 0; i < RP; i++)
        #pragma unroll
        for (int j = 0; j < 4; j++) acc2[i][j] = 0ULL;

    float av[4 * RP], wv[8];
    #pragma unroll
    for (int l = 0; l < 4 * RP; l++) {
        int idx = tid + l * 256;
        av[l] = A[(size_t)(m0 + (idx >> 5)) * K + (idx & 31)];
    }
    #pragma unroll
    for (int l = 0; l < 8; l++) {
        int idx = tid + l * 256;
        wv[l] = W[(size_t)(n0 + (idx >> 5)) * K + (idx & 31)];
    }

    for (int kt = 0; kt < K; kt += 32) {
        __syncthreads();
        #pragma unroll
        for (int l = 0; l < 4 * RP; l++) {
            int idx = tid + l * 256;
            As[idx & 31][idx >> 5] = av[l];
        }
        #pragma unroll
        for (int l = 0; l < 8; l++) {
            int idx = tid + l * 256;
            Bs[idx & 31][idx >> 5] = make_float2(wv[l], wv[l]);
        }
        __syncthreads();
        if (kt + 32 < K) {
            int kn = kt + 32;
            #pragma unroll
            for (int l = 0; l < 4 * RP; l++) {
                int idx = tid + l * 256;
                av[l] = A[(size_t)(m0 + (idx >> 5)) * K + kn + (idx & 31)];
            }
            #pragma unroll
            for (int l = 0; l < 8; l++) {
                int idx = tid + l * 256;
                wv[l] = W[(size_t)(n0 + (idx >> 5)) * K + kn + (idx & 31)];
            }
        }
        #pragma unroll 8
        for (int k = 0; k < 32; k++) {
            f32x2 a2[RP];
            #pragma unroll
            for (int ip = 0; ip < RP; ip++)
                a2[ip] = *(const f32x2*)&As[k][ty * 2 * RP + 2 * ip];
            f32x2 bd[4];
            #pragma unroll
            for (int j = 0; j < 4; j++)
                bd[j] = *(const f32x2*)&Bs[k][tx + 16 * j];
            #pragma unroll
            for (int j = 0; j < 4; j++)
                #pragma unroll
                for (int ip = 0; ip < RP; ip++)
                    fma2(acc2[ip][j], a2[ip], bd[j]);
        }
    }
    const float* res = nullptr;
    if (EPI & EPI_RES) res = bufsel(res_sel);
    float cin = (EPI & EPI_COORD) ? g_consts[0] : 0.0f;
    #pragma unroll
    for (int ip = 0; ip < RP; ip++) {
        #pragma unroll
        for (int j = 0; j < 4; j++) {
            float v0, v1;
            unpack2(acc2[ip][j], v0, v1);
            int col = n0 + tx + 16 * j;
            #pragma unroll
            for (int rr = 0; rr < 2; rr++) {
                int row = m0 + ty * 2 * RP + ip * 2 + rr;
                float v = rr ? v1 : v0;
                if (EPI & EPI_BIAS) v += bias[col];
                if (EPI & EPI_COORD) {
                    v += cin * (x3[row * 3 + 0] * cw3[col * 3 + 0] +
                                x3[row * 3 + 1] * cw3[col * 3 + 1] +
                                x3[row * 3 + 2] * cw3[col * 3 + 2]) + cb3[col];
                }
                if (EPI & EPI_GELU) v = gelu_exact(v);
                if (EPI & EPI_RES) v += res[(size_t)row * N + col];
                C[(size_t)row * N + col] = v;
            }
        }
    }
}

// ---------------- adaLN (h -> h1), one block per row ----------------
__global__ void k_adaln(const float* __restrict__ gamma, const float* __restrict__ beta,
                        int b, int which) {
    __shared__ float red[2][8];
    int row = blockIdx.x, t = threadIdx.x;
    int lane = t & 31, wid = t >> 5;
    float x = g_h[(size_t)row * 256 + t];
    float s1 = x, s2 = x * x;
    #pragma unroll
    for (int off = 16; off > 0; off >>= 1) {
        s1 += __shfl_xor_sync(0xffffffffu, s1, off);
        s2 += __shfl_xor_sync(0xffffffffu, s2, off);
    }
    if (lane == 0) { red[0][wid] = s1; red[1][wid] = s2; }
    __syncthreads();
    float S = 0.0f, Q = 0.0f;
    #pragma unroll
    for (int w = 0; w < 8; w++) { S += red[0][w]; Q += red[1][w]; }
    float mu = S * (1.0f / 256.0f);
    float var = Q * (1.0f / 256.0f) - mu * mu;
    float rs = rsqrtf(var + 1e-5f);
    const float* ss = which ? g_ss2[b] : g_ss1[b];
    float scale = ss[t], shift = ss[256 + t];
    g_h1[(size_t)row * 256 + t] =
        ((x - mu) * rs * gamma[t] + beta[t]) * (1.0f + scale) + shift;
}

// ---------------- attention: grid (L/32, NH) = 512 CTAs, 256 threads ----------------
// i-tile 32 for occupancy. Phase A: thread=(row iA, j-lane jg in 8); bs stride 72
// makes the exp RMW bank-perfect. Phase B: thread=(row iA, d-slice dg in 4, j-half jh);
// combine jh by shuffle. Unnormalized softmax (logits provably small).
__global__ void __launch_bounds__(256) k_attn(int b) {
    __shared__ __align__(16) float qs[32][34];
    __shared__ __align__(16) float ks[64][36];
    __shared__ __align__(16) float vs[64][32];
    __shared__ __align__(16) float bs[32][72];

    int i0 = blockIdx.x * 32, h = blockIdx.y;
    const __half* bias = g_bias + (size_t)(b * NH + h) * L2;
    int tid = threadIdx.x;

    #pragma unroll
    for (int l = 0; l < 4; l++) {
        int idx = tid + l * 256;
        int r = idx >> 5, c = idx & 31;
        qs[r][c] = g_q[(size_t)(i0 + r) * 256 + h * 32 + c];
    }
    __syncthreads();

    int iA = tid >> 3, jg = tid & 7;          // phase A mapping
    int dg = tid & 3, jh = (tid >> 2) & 1;    // phase B mapping
    f32x2 qr[16];
    #pragma unroll
    for (int c = 0; c < 16; c++) qr[c] = *(const f32x2*)&qs[iA][2 * c];

    f32x2 o2[4] = {0ULL, 0ULL, 0ULL, 0ULL};   // d = dg*8 .. dg*8+7
    float lsum = 0.0f;
    const float scale = 0.1767766952966369f;  // 1/sqrt(32)

    for (int jt = 0; jt < 32; jt++) {
        int j0 = jt * 64;
        __syncthreads();
        #pragma unroll
        for (int l = 0; l < 8; l++) {
            int idx = tid + l * 256;
            int r = idx >> 5, c = idx & 31;
            ks[r][c] = g_k[(size_t)(j0 + r) * 256 + h * 32 + c];
            vs[r][c] = g_v[(size_t)(j0 + r) * 256 + h * 32 + c];
        }
        #pragma unroll
        for (int l = 0; l < 4; l++) {
            int idx = tid + l * 256;
            int r = idx >> 5, c2 = idx & 31;
            __half2 hv = *(const __half2*)(bias + (size_t)(i0 + r) * L + j0 + 2 * c2);
            *(float2*)&bs[r][2 * c2] = __half22float2(hv);
        }
        __syncthreads();

        // phase A: s = q.k, p = exp(s*scale + bias) written in place to bs
        #pragma unroll 2
        for (int jj = 0; jj < 8; jj++) {
            int j = jg + 8 * jj;
            f32x2 accA = 0ULL, accB = 0ULL;
            const float4* kp4 = (const float4*)&ks[j][0];
            #pragma unroll
            for (int c = 0; c < 8; c++) {
                float4 kv = kp4[c];
                fma2(accA, qr[2 * c], f2lo(kv));
                fma2(accB, qr[2 * c + 1], f2hi(kv));
            }
            float a0, a1, b0, b1;
            unpack2(accA, a0, a1);
            unpack2(accB, b0, b1);
            float s = (a0 + a1) + (b0 + b1);
            float pv = __expf(s * scale + bs[iA][j]);
            bs[iA][j] = pv;
            lsum += pv;
        }
        __syncthreads();
        // phase B: o += p_j * v_j over half the j's (jh split)
        const int jbase = jh * 32;
        #pragma unroll 4
        for (int jj = 0; jj < 32; jj++) {
            int j = jbase + jj;
            float p = bs[iA][j];
            f32x2 pd = pack2(p, p);
            const float4* vp4 = (const float4*)&vs[j][dg * 8];
            float4 v0 = vp4[0], v1 = vp4[1];
            fma2(o2[0], pd, f2lo(v0));
            fma2(o2[1], pd, f2hi(v0));
            fma2(o2[2], pd, f2lo(v1));
            fma2(o2[3], pd, f2hi(v1));
        }
    }
    // combine jh halves (lane^4 flips jh, same iA/dg)
    #pragma unroll
    for (int c = 0; c < 4; c++)
        add2(o2[c], __shfl_xor_sync(0xffffffffu, o2[c], 4));
    // lsum: reduce over 8 lanes sharing iA
    lsum += __shfl_xor_sync(0xffffffffu, lsum, 1);
    lsum += __shfl_xor_sync(0xffffffffu, lsum, 2);
    lsum += __shfl_xor_sync(0xffffffffu, lsum, 4);
    float inv = 1.0f / lsum;
    if (jh == 0) {
        float* op = g_o + (size_t)(i0 + iA) * 256 + h * 32 + dg * 8;
        #pragma unroll
        for (int q = 0; q < 4; q++) {
            float lo, hi;
            unpack2(o2[q], lo, hi);
            *(float2*)(op + 2 * q) = make_float2(lo * inv, hi * inv);
        }
    }
}

// ---------------- final projection ----------------
__global__ void k_final(const float* __restrict__ x, const float* __restrict__ oW,
                        const float* __restrict__ ob, float* __restrict__ out) {
    int row = blockIdx.x;
    int w = threadIdx.x >> 5, lane = threadIdx.x & 31;
    const float* hr = g_h + (size_t)row * 256;
    const float* wr = oW + w * 256;
    float acc = 0.0f;
    #pragma unroll
    for (int c = lane; c < 256; c += 32) acc += hr[c] * wr[c];
    #pragma unroll
    for (int off = 16; off > 0; off >>= 1)
        acc += __shfl_down_sync(0xffffffffu, acc, off);
    if (lane == 0)
        out[row * 3 + w] = g_consts[1] * x[row * 3 + w] + g_consts[2] * (acc + ob[w]);
}

// ---------------- host launcher ----------------
extern "C" void kernel_launch(void* const* d_in, const int* in_sizes, int n_in,
                              void* d_out, int out_size) {
    const float* x_noisy  = (const float*)d_in[0];
    const float* sigma    = (const float*)d_in[1];
    const float* single   = (const float*)d_in[2];
    const float* pair     = (const float*)d_in[3];
    const float* coord_W  = (const float*)d_in[4];
    const float* coord_b  = (const float*)d_in[5];
    const float* single_W = (const float*)d_in[6];
    const float* single_b = (const float*)d_in[7];
    const float* tmlp_W1  = (const float*)d_in[8];
    const float* tmlp_b1  = (const float*)d_in[9];
    const float* tmlp_W2  = (const float*)d_in[10];
    const float* tmlp_b2  = (const float*)d_in[11];
    const float* ada1_g   = (const float*)d_in[12];
    const float* ada1_b   = (const float*)d_in[13];
    const float* ada1_pW  = (const float*)d_in[14];
    const float* ada1_pb  = (const float*)d_in[15];
    const float* qW       = (const float*)d_in[16];
    const float* kW       = (const float*)d_in[17];
    const float* vW       = (const float*)d_in[18];
    const float* pairW    = (const float*)d_in[19];
    const float* outW     = (const float*)d_in[20];
    const float* outb     = (const float*)d_in[21];
    const float* ada2_g   = (const float*)d_in[22];
    const float* ada2_b   = (const float*)d_in[23];
    const float* ada2_pW  = (const float*)d_in[24];
    const float* ada2_pb  = (const float*)d_in[25];
    const float* ffn_W1   = (const float*)d_in[26];
    const float* ffn_b1   = (const float*)d_in[27];
    const float* ffn_W2   = (const float*)d_in[28];
    const float* ffn_b2   = (const float*)d_in[29];
    const float* out_W    = (const float*)d_in[30];
    const float* out_b    = (const float*)d_in[31];
    float* out = (float*)d_out;

    k_setup<<<1, 1024>>>(sigma, tmlp_W1, tmlp_b1, tmlp_W2, tmlp_b2);   // 0
    k_ada<<<512, 256>>>(ada1_pW, ada1_pb, ada2_pW, ada2_pb);           // 1
    k_pairbias<<<(int)(L2 / 128), 128>>>(pair, pairW);                 // 2
    // 3 <- profiled: init GEMM, now RP=1 / 256 CTAs (A/B vs R11's 35us @128 CTAs)
    k_gemm<1, EPI_BIAS | EPI_COORD><<<dim3(4, 64, 1), 256>>>(
        single, -1, single_W, single_W, single_W, single_b, -1, 0, 256, 256,
        x_noisy, coord_W, coord_b);

    for (int b = 0; b < NB; b++) {
        k_adaln<<<L, 256>>>(ada1_g + b * 256, ada1_b + b * 256, b, 0);
        // fused q/k/v: RP=2, (4,32,3) = 384 CTAs
        k_gemm<2, 0><<<dim3(4, 32, 3), 256>>>(
            nullptr, 1, qW + (size_t)b * 65536, kW + (size_t)b * 65536,
            vW + (size_t)b * 65536, nullptr, -1, 2, 256, 256,
            nullptr, nullptr, nullptr);
        k_attn<<<dim3(64, 8), 256>>>(b);
        // out proj: RP=1, (4,64) = 256 CTAs
        k_gemm<1, EPI_BIAS | EPI_RES><<<dim3(4, 64, 1), 256>>>(
            nullptr, 5, outW + (size_t)b * 65536, outW, outW, outb + b * 256,
            0, 0, 256, 256, nullptr, nullptr, nullptr);
        k_adaln<<<L, 256>>>(ada2_g + b * 256, ada2_b + b * 256, b, 1);
        // ffn1: RP=2, (16,32) = 512 CTAs
        k_gemm<2, EPI_BIAS | EPI_GELU><<<dim3(16, 32, 1), 256>>>(
            nullptr, 1, ffn_W1 + (size_t)b * 262144, ffn_W1, ffn_W1,
            ffn_b1 + b * 1024, -1, 6, 256, 1024, nullptr, nullptr, nullptr);
        // ffn2: RP=1, (4,64) = 256 CTAs, K=1024
        k_gemm<1, EPI_BIAS | EPI_RES><<<dim3(4, 64, 1), 256>>>(
            nullptr, 6, ffn_W2 + (size_t)b * 262144, ffn_W2, ffn_W2,
            ffn_b2 + b * 256, 0, 0, 1024, 256, nullptr, nullptr, nullptr);
    }
    k_final<<<L, 96>>>(x_noisy, out_W, out_b, out);
}

// round 16
// speedup vs baseline: 1.4188x; 1.4188x over previous
#include <cuda_runtime.h>
#include <cuda_fp16.h>
#include <math.h>

#define L 2048
#define CA 256
#define NH 8
#define HD 32
#define NB 4
static const size_t L2 = (size_t)L * L;

// ---------------- scratch (device globals; no allocation allowed) ----------------
__device__ float g_consts[4];           // c_in, c_skip, c_out, c_noise
__device__ float g_tc[256];
__device__ float g_ss1[NB][512];
__device__ float g_ss2[NB][512];
__device__ float g_h[L * CA];
__device__ float g_h1[L * CA];
__device__ float g_q[L * CA];
__device__ float g_k[L * CA];
__device__ float g_v[L * CA];
__device__ float g_o[L * CA];
__device__ float g_ffn[L * 1024];
__device__ __half g_bias[134217728];    // [NB*NH][L][L] fp16 = 256 MB

__device__ __forceinline__ float* bufsel(int s) {
    switch (s) {
        case 0: return g_h;
        case 1: return g_h1;
        case 2: return g_q;
        case 3: return g_k;
        case 4: return g_v;
        case 5: return g_o;
        case 6: return g_ffn;
    }
    return nullptr;
}

// ---------------- packed f32x2 helpers (FFMA2) ----------------
typedef unsigned long long f32x2;

__device__ __forceinline__ f32x2 pack2(float lo, float hi) {
    f32x2 r;
    asm("mov.b64 %0, {%1, %2};" : "=l"(r) : "f"(lo), "f"(hi));
    return r;
}
__device__ __forceinline__ void unpack2(f32x2 v, float& a, float& b) {
    asm("mov.b64 {%0, %1}, %2;" : "=f"(a), "=f"(b) : "l"(v));
}
__device__ __forceinline__ void fma2(f32x2& d, f32x2 a, f32x2 b) {
    asm("fma.rn.f32x2 %0, %1, %2, %3;" : "=l"(d) : "l"(a), "l"(b), "l"(d));
}
__device__ __forceinline__ f32x2 f2lo(float4 v) { return pack2(v.x, v.y); }
__device__ __forceinline__ f32x2 f2hi(float4 v) { return pack2(v.z, v.w); }

__device__ __forceinline__ float gelu_exact(float x) {
    return 0.5f * x * (1.0f + erff(x * 0.7071067811865475f));
}

__device__ __forceinline__ unsigned tf32of(float f) {
    unsigned r;
    asm("cvt.rna.tf32.f32 %0, %1;" : "=r"(r) : "f"(f));
    return r;
}

__device__ __forceinline__ void mma_tf32(float* d, unsigned a0, unsigned a1,
                                         unsigned a2, unsigned a3,
                                         unsigned b0, unsigned b1) {
    asm volatile(
        "mma.sync.aligned.m16n8k8.row.col.f32.tf32.tf32.f32 "
        "{%0,%1,%2,%3}, {%4,%5,%6,%7}, {%8,%9}, {%0,%1,%2,%3};"
        : "+f"(d[0]), "+f"(d[1]), "+f"(d[2]), "+f"(d[3])
        : "r"(a0), "r"(a1), "r"(a2), "r"(a3), "r"(b0), "r"(b1));
}

// ---------------- merged setup: consts + time MLP (1 CTA, 1024 threads) ----------------
__global__ void k_setup(const float* __restrict__ sigma,
                        const float* __restrict__ W1, const float* __restrict__ b1,
                        const float* __restrict__ W2, const float* __restrict__ b2) {
    __shared__ float temb[256];
    __shared__ float hid[1024];
    int t = threadIdx.x;
    float s = sigma[0];
    if (t == 0) {
        float s2 = s * s + 256.0f;
        g_consts[0] = rsqrtf(s2);               // c_in
        g_consts[1] = 256.0f / s2;              // c_skip
        g_consts[2] = s * 16.0f * rsqrtf(s2);   // c_out
        g_consts[3] = 0.25f * logf(s + 1e-8f);  // c_noise
    }
    float cn = 0.25f * logf(s + 1e-8f);
    if (t < 256) {
        int j = t & 127;
        float f = expf(-logf(10000.0f) * (float)j / 128.0f);
        float a = cn * f;
        temb[t] = (t < 128) ? cosf(a) : sinf(a);
    }
    __syncthreads();
    {
        const float* w = W1 + (size_t)t * 256;
        float acc = 0.0f;
        #pragma unroll 8
        for (int c = 0; c < 256; c++) acc += temb[c] * w[c];
        hid[t] = gelu_exact(acc + b1[t]);
    }
    __syncthreads();
    if (t < 256) {
        const float* w = W2 + (size_t)t * 1024;
        float acc = 0.0f;
        #pragma unroll 8
        for (int c = 0; c < 1024; c++) acc += hid[c] * w[c];
        g_tc[t] = acc + b2[t];
    }
}

// ada scale/shift: one warp per output row, coalesced weight reads.
__global__ void k_ada(const float* __restrict__ pW1, const float* __restrict__ pb1,
                      const float* __restrict__ pW2, const float* __restrict__ pb2) {
    int wid = threadIdx.x >> 5, lane = threadIdx.x & 31;
    int gid = blockIdx.x * 8 + wid;   // 0..4095
    int blk = gid >> 10;
    int which = (gid >> 9) & 1;
    int idx = gid & 511;
    const float* W = which ? pW2 : pW1;
    const float* pb = which ? pb2 : pb1;
    const float* w = W + ((size_t)blk * 512 + idx) * 256;
    float acc = 0.0f;
    #pragma unroll
    for (int c = lane; c < 256; c += 32) acc += g_tc[c] * w[c];
    #pragma unroll
    for (int off = 16; off > 0; off >>= 1)
        acc += __shfl_xor_sync(0xffffffffu, acc, off);
    if (lane == 0) {
        float val = acc + pb[blk * 512 + idx];
        if (which) g_ss2[blk][idx] = val; else g_ss1[blk][idx] = val;
    }
}

// ---------------- pair bias via tensor cores (tf32 mma.sync) ----------------
__global__ void __launch_bounds__(128) k_pairbias(const float* __restrict__ pair,
                                                  const float* __restrict__ pW) {
    __shared__ __align__(16) char sm[34816 + 8704];  // As | Bs ; Ds aliases As
    unsigned (*As)[68] = (unsigned(*)[68])sm;          // [128][68]
    unsigned (*Bs)[68] = (unsigned(*)[68])(sm + 34816);// [32][68]
    __half   (*Ds)[136] = (__half(*)[136])sm;          // [32][136] aliases As

    size_t r0 = (size_t)blockIdx.x * 128;
    int tid = threadIdx.x, lane = tid & 31, w = tid >> 5;

    const float4* Ap4 = (const float4*)(pair + r0 * 64);
    #pragma unroll
    for (int l = 0; l < 16; l++) {
        int idx = tid + l * 128;
        float4 v = Ap4[idx];
        int r = idx >> 4, c4 = (idx & 15) * 4;
        uint4 t4 = make_uint4(tf32of(v.x), tf32of(v.y), tf32of(v.z), tf32of(v.w));
        *(uint4*)&As[r][c4] = t4;
    }
    #pragma unroll
    for (int l = 0; l < 16; l++) {
        int idx = tid + l * 128;
        Bs[idx >> 6][idx & 63] = tf32of(pW[idx]);
    }
    __syncthreads();

    float acc[2][4][4];
    #pragma unroll
    for (int mt = 0; mt < 2; mt++)
        #pragma unroll
        for (int nt = 0; nt < 4; nt++)
            #pragma unroll
            for (int q = 0; q < 4; q++) acc[mt][nt][q] = 0.0f;

    int qr_ = lane >> 2, qc = lane & 3;
    #pragma unroll
    for (int k = 0; k < 8; k++) {
        int kc = k * 8 + qc;
        unsigned b0[4], b1[4];
        #pragma unroll
        for (int nt = 0; nt < 4; nt++) {
            b0[nt] = Bs[nt * 8 + qr_][kc];
            b1[nt] = Bs[nt * 8 + qr_][kc + 4];
        }
        #pragma unroll
        for (int mt = 0; mt < 2; mt++) {
            int mr = w * 32 + mt * 16 + qr_;
            unsigned a0 = As[mr][kc];
            unsigned a1 = As[mr + 8][kc];
            unsigned a2 = As[mr][kc + 4];
            unsigned a3 = As[mr + 8][kc + 4];
            #pragma unroll
            for (int nt = 0; nt < 4; nt++)
                mma_tf32(acc[mt][nt], a0, a1, a2, a3, b0[nt], b1[nt]);
        }
    }
    __syncthreads();

    #pragma unroll
    for (int mt = 0; mt < 2; mt++) {
        int r = w * 32 + mt * 16 + qr_;
        #pragma unroll
        for (int nt = 0; nt < 4; nt++) {
            int n = nt * 8 + qc * 2;
            Ds[n][r]         = __float2half(acc[mt][nt][0]);
            Ds[n + 1][r]     = __float2half(acc[mt][nt][1]);
            Ds[n][r + 8]     = __float2half(acc[mt][nt][2]);
            Ds[n + 1][r + 8] = __float2half(acc[mt][nt][3]);
        }
    }
    __syncthreads();
    #pragma unroll
    for (int l = 0; l < 16; l++) {
        int idx = tid + l * 128;
        int plane = idx >> 6, off = (idx & 63) * 2;
        __half2 hv = __halves2half2(Ds[plane][off], Ds[plane][off + 1]);
        *(__half2*)(g_bias + (size_t)plane * L2 + r0 + off) = hv;
    }
}

// ---------------- tensor-core GEMM: C[M,N] = epi(A[M,K] @ W[N,K]^T) ----------------
// BM=64, BN=64, BK=32, 256 threads (8 warps, each 32x16 warp-tile of m16n8k8).
#define EPI_BIAS  1
#define EPI_GELU  2
#define EPI_RES   4
#define EPI_COORD 8

template <int EPI>
__global__ void __launch_bounds__(256) k_gemm_tc(
                       const float* __restrict__ Aext, int a_sel,
                       const float* __restrict__ Wa, const float* __restrict__ Wb,
                       const float* __restrict__ Wc,
                       const float* __restrict__ bias,
                       int res_sel, int c_sel0, int K, int N,
                       const float* __restrict__ x3,
                       const float* __restrict__ cw3,
                       const float* __restrict__ cb3) {
    __shared__ __align__(16) unsigned As[64][36];
    __shared__ __align__(16) unsigned Bs[64][36];
    const float* A = (a_sel >= 0) ? bufsel(a_sel) : Aext;
    int z = blockIdx.z;
    const float* W = (z == 0) ? Wa : (z == 1 ? Wb : Wc);
    float* C = bufsel(c_sel0 + z);
    int m0 = blockIdx.y * 64, n0 = blockIdx.x * 64;
    int tid = threadIdx.x, lane = tid & 31, wid = tid >> 5;
    int wm = wid & 1, wn = wid >> 1;      // wm: 32-row block, wn: 16-col block
    int qr = lane >> 2, qc = lane & 3;

    float acc[2][2][4];
    #pragma unroll
    for (int mt = 0; mt < 2; mt++)
        #pragma unroll
        for (int nt = 0; nt < 2; nt++)
            #pragma unroll
            for (int q = 0; q < 4; q++) acc[mt][nt][q] = 0.0f;

    float av[8], wv[8];
    #pragma unroll
    for (int l = 0; l < 8; l++) {
        int idx = tid + l * 256;
        int r = idx >> 5, c = idx & 31;
        av[l] = A[(size_t)(m0 + r) * K + c];
        wv[l] = W[(size_t)(n0 + r) * K + c];
    }

    for (int kt = 0; kt < K; kt += 32) {
        __syncthreads();
        #pragma unroll
        for (int l = 0; l < 8; l++) {
            int idx = tid + l * 256;
            int r = idx >> 5, c = idx & 31;
            As[r][c] = tf32of(av[l]);
            Bs[r][c] = tf32of(wv[l]);
        }
        __syncthreads();
        if (kt + 32 < K) {
            int kn = kt + 32;
            #pragma unroll
            for (int l = 0; l < 8; l++) {
                int idx = tid + l * 256;
                int r = idx >> 5, c = idx & 31;
                av[l] = A[(size_t)(m0 + r) * K + kn + c];
                wv[l] = W[(size_t)(n0 + r) * K + kn + c];
            }
        }
        #pragma unroll
        for (int ks = 0; ks < 4; ks++) {
            int kc = ks * 8 + qc;
            unsigned b0[2], b1[2];
            #pragma unroll
            for (int nt = 0; nt < 2; nt++) {
                int nr = wn * 16 + nt * 8 + qr;
                b0[nt] = Bs[nr][kc];
                b1[nt] = Bs[nr][kc + 4];
            }
            #pragma unroll
            for (int mt = 0; mt < 2; mt++) {
                int mr = wm * 32 + mt * 16 + qr;
                unsigned a0 = As[mr][kc];
                unsigned a1 = As[mr + 8][kc];
                unsigned a2 = As[mr][kc + 4];
                unsigned a3 = As[mr + 8][kc + 4];
                #pragma unroll
                for (int nt = 0; nt < 2; nt++)
                    mma_tf32(acc[mt][nt], a0, a1, a2, a3, b0[nt], b1[nt]);
            }
        }
    }
    const float* res = nullptr;
    if (EPI & EPI_RES) res = bufsel(res_sel);
    float cin = (EPI & EPI_COORD) ? g_consts[0] : 0.0f;
    #pragma unroll
    for (int mt = 0; mt < 2; mt++) {
        #pragma unroll
        for (int nt = 0; nt < 2; nt++) {
            int col = n0 + wn * 16 + nt * 8 + qc * 2;
            #pragma unroll
            for (int half = 0; half < 2; half++) {
                int row = m0 + wm * 32 + mt * 16 + qr + half * 8;
                float v0 = acc[mt][nt][half * 2];
                float v1 = acc[mt][nt][half * 2 + 1];
                if (EPI & EPI_BIAS) { v0 += bias[col]; v1 += bias[col + 1]; }
                if (EPI & EPI_COORD) {
                    float xr0 = x3[row * 3 + 0], xr1 = x3[row * 3 + 1], xr2 = x3[row * 3 + 2];
                    v0 += cin * (xr0 * cw3[col * 3 + 0] + xr1 * cw3[col * 3 + 1] +
                                 xr2 * cw3[col * 3 + 2]) + cb3[col];
                    v1 += cin * (xr0 * cw3[(col + 1) * 3 + 0] + xr1 * cw3[(col + 1) * 3 + 1] +
                                 xr2 * cw3[(col + 1) * 3 + 2]) + cb3[col + 1];
                }
                if (EPI & EPI_GELU) { v0 = gelu_exact(v0); v1 = gelu_exact(v1); }
                if (EPI & EPI_RES) {
                    const float* rp = res + (size_t)row * N + col;
                    v0 += rp[0]; v1 += rp[1];
                }
                *(float2*)(C + (size_t)row * N + col) = make_float2(v0, v1);
            }
        }
    }
}

// ---------------- adaLN (h -> h1), one block per row ----------------
__global__ void k_adaln(const float* __restrict__ gamma, const float* __restrict__ beta,
                        int b, int which) {
    __shared__ float red[2][8];
    int row = blockIdx.x, t = threadIdx.x;
    int lane = t & 31, wid = t >> 5;
    float x = g_h[(size_t)row * 256 + t];
    float s1 = x, s2 = x * x;
    #pragma unroll
    for (int off = 16; off > 0; off >>= 1) {
        s1 += __shfl_xor_sync(0xffffffffu, s1, off);
        s2 += __shfl_xor_sync(0xffffffffu, s2, off);
    }
    if (lane == 0) { red[0][wid] = s1; red[1][wid] = s2; }
    __syncthreads();
    float S = 0.0f, Q = 0.0f;
    #pragma unroll
    for (int w = 0; w < 8; w++) { S += red[0][w]; Q += red[1][w]; }
    float mu = S * (1.0f / 256.0f);
    float var = Q * (1.0f / 256.0f) - mu * mu;
    float rs = rsqrtf(var + 1e-5f);
    const float* ss = which ? g_ss2[b] : g_ss1[b];
    float scale = ss[t], shift = ss[256 + t];
    g_h1[(size_t)row * 256 + t] =
        ((x - mu) * rs * gamma[t] + beta[t]) * (1.0f + scale) + shift;
}

// ---------------- attention: grid (L/64, NH) = 256 CTAs, 256 threads (R14 best) ----
__global__ void __launch_bounds__(256) k_attn(int b) {
    __shared__ __align__(16) float qs[64][34];
    __shared__ __align__(16) float ks[64][36];
    __shared__ __align__(16) float vs[64][32];
    __shared__ __align__(16) float bs[64][66];

    int i0 = blockIdx.x * 64, h = blockIdx.y;
    const __half* bias = g_bias + (size_t)(b * NH + h) * L2;
    int tid = threadIdx.x;

    #pragma unroll
    for (int l = 0; l < 8; l++) {
        int idx = tid + l * 256;
        int r = idx >> 5, c = idx & 31;
        qs[r][c] = g_q[(size_t)(i0 + r) * 256 + h * 32 + c];
    }
    __syncthreads();

    int iA = tid >> 2, jg = tid & 3;
    f32x2 qr[16];
    #pragma unroll
    for (int c = 0; c < 16; c++) qr[c] = *(const f32x2*)&qs[iA][2 * c];

    f32x2 o2[4] = {0ULL, 0ULL, 0ULL, 0ULL};
    float lsum = 0.0f;
    const float scale = 0.1767766952966369f;  // 1/sqrt(32)

    for (int jt = 0; jt < 32; jt++) {
        int j0 = jt * 64;
        __syncthreads();
        #pragma unroll
        for (int l = 0; l < 8; l++) {
            int idx = tid + l * 256;
            int r = idx >> 5, c = idx & 31;
            ks[r][c] = g_k[(size_t)(j0 + r) * 256 + h * 32 + c];
            vs[r][c] = g_v[(size_t)(j0 + r) * 256 + h * 32 + c];
        }
        #pragma unroll
        for (int l = 0; l < 8; l++) {
            int idx = tid + l * 256;
            int r = idx >> 5, c2 = idx & 31;
            __half2 hv = *(const __half2*)(bias + (size_t)(i0 + r) * L + j0 + 2 * c2);
            *(float2*)&bs[r][2 * c2] = __half22float2(hv);
        }
        __syncthreads();

        #pragma unroll 2
        for (int jj = 0; jj < 16; jj++) {
            int j = jg + 4 * jj;
            f32x2 accA = 0ULL, accB = 0ULL;
            const float4* kp4 = (const float4*)&ks[j][0];
            #pragma unroll
            for (int c = 0; c < 8; c++) {
                float4 kv = kp4[c];
                fma2(accA, qr[2 * c], f2lo(kv));
                fma2(accB, qr[2 * c + 1], f2hi(kv));
            }
            float a0, a1, b0, b1;
            unpack2(accA, a0, a1);
            unpack2(accB, b0, b1);
            float s = (a0 + a1) + (b0 + b1);
            float pv = __expf(s * scale + bs[iA][j]);
            bs[iA][j] = pv;
            lsum += pv;
        }
        __syncthreads();
        #pragma unroll 4
        for (int j = 0; j < 64; j++) {
            float p = bs[iA][j];
            f32x2 pd = pack2(p, p);
            const float4* vp4 = (const float4*)&vs[j][jg * 8];
            float4 v0 = vp4[0], v1 = vp4[1];
            fma2(o2[0], pd, f2lo(v0));
            fma2(o2[1], pd, f2hi(v0));
            fma2(o2[2], pd, f2lo(v1));
            fma2(o2[3], pd, f2hi(v1));
        }
    }
    lsum += __shfl_xor_sync(0xffffffffu, lsum, 1);
    lsum += __shfl_xor_sync(0xffffffffu, lsum, 2);
    float inv = 1.0f / lsum;
    float* op = g_o + (size_t)(i0 + iA) * 256 + h * 32 + jg * 8;
    #pragma unroll
    for (int q = 0; q < 4; q++) {
        float lo, hi;
        unpack2(o2[q], lo, hi);
        *(float2*)(op + 2 * q) = make_float2(lo * inv, hi * inv);
    }
}

// ---------------- final projection ----------------
__global__ void k_final(const float* __restrict__ x, const float* __restrict__ oW,
                        const float* __restrict__ ob, float* __restrict__ out) {
    int row = blockIdx.x;
    int w = threadIdx.x >> 5, lane = threadIdx.x & 31;
    const float* hr = g_h + (size_t)row * 256;
    const float* wr = oW + w * 256;
    float acc = 0.0f;
    #pragma unroll
    for (int c = lane; c < 256; c += 32) acc += hr[c] * wr[c];
    #pragma unroll
    for (int off = 16; off > 0; off >>= 1)
        acc += __shfl_down_sync(0xffffffffu, acc, off);
    if (lane == 0)
        out[row * 3 + w] = g_consts[1] * x[row * 3 + w] + g_consts[2] * (acc + ob[w]);
}

// ---------------- host launcher ----------------
extern "C" void kernel_launch(void* const* d_in, const int* in_sizes, int n_in,
                              void* d_out, int out_size) {
    const float* x_noisy  = (const float*)d_in[0];
    const float* sigma    = (const float*)d_in[1];
    const float* single   = (const float*)d_in[2];
    const float* pair     = (const float*)d_in[3];
    const float* coord_W  = (const float*)d_in[4];
    const float* coord_b  = (const float*)d_in[5];
    const float* single_W = (const float*)d_in[6];
    const float* single_b = (const float*)d_in[7];
    const float* tmlp_W1  = (const float*)d_in[8];
    const float* tmlp_b1  = (const float*)d_in[9];
    const float* tmlp_W2  = (const float*)d_in[10];
    const float* tmlp_b2  = (const float*)d_in[11];
    const float* ada1_g   = (const float*)d_in[12];
    const float* ada1_b   = (const float*)d_in[13];
    const float* ada1_pW  = (const float*)d_in[14];
    const float* ada1_pb  = (const float*)d_in[15];
    const float* qW       = (const float*)d_in[16];
    const float* kW       = (const float*)d_in[17];
    const float* vW       = (const float*)d_in[18];
    const float* pairW    = (const float*)d_in[19];
    const float* outW     = (const float*)d_in[20];
    const float* outb     = (const float*)d_in[21];
    const float* ada2_g   = (const float*)d_in[22];
    const float* ada2_b   = (const float*)d_in[23];
    const float* ada2_pW  = (const float*)d_in[24];
    const float* ada2_pb  = (const float*)d_in[25];
    const float* ffn_W1   = (const float*)d_in[26];
    const float* ffn_b1   = (const float*)d_in[27];
    const float* ffn_W2   = (const float*)d_in[28];
    const float* ffn_b2   = (const float*)d_in[29];
    const float* out_W    = (const float*)d_in[30];
    const float* out_b    = (const float*)d_in[31];
    float* out = (float*)d_out;

    k_setup<<<1, 1024>>>(sigma, tmlp_W1, tmlp_b1, tmlp_W2, tmlp_b2);   // 0
    k_ada<<<512, 256>>>(ada1_pW, ada1_pb, ada2_pW, ada2_pb);           // 1
    k_pairbias<<<(int)(L2 / 128), 128>>>(pair, pairW);                 // 2
    // 3 <- profiled: tensor-core init GEMM
    k_gemm_tc<EPI_BIAS | EPI_COORD><<<dim3(4, 32, 1), 256>>>(
        single, -1, single_W, single_W, single_W, single_b, -1, 0, 256, 256,
        x_noisy, coord_W, coord_b);

    for (int b = 0; b < NB; b++) {
        k_adaln<<<L, 256>>>(ada1_g + b * 256, ada1_b + b * 256, b, 0);
        // fused q/k/v: (4,32,3) = 384 CTAs
        k_gemm_tc<0><<<dim3(4, 32, 3), 256>>>(
            nullptr, 1, qW + (size_t)b * 65536, kW + (size_t)b * 65536,
            vW + (size_t)b * 65536, nullptr, -1, 2, 256, 256,
            nullptr, nullptr, nullptr);
        k_attn<<<dim3(32, 8), 256>>>(b);
        // h = h + o @ outW^T + outb
        k_gemm_tc<EPI_BIAS | EPI_RES><<<dim3(4, 32, 1), 256>>>(
            nullptr, 5, outW + (size_t)b * 65536, outW, outW, outb + b * 256,
            0, 0, 256, 256, nullptr, nullptr, nullptr);
        k_adaln<<<L, 256>>>(ada2_g + b * 256, ada2_b + b * 256, b, 1);
        // ffn1: gelu(h2 @ W1^T + b1) -> (16,32) = 512 CTAs
        k_gemm_tc<EPI_BIAS | EPI_GELU><<<dim3(16, 32, 1), 256>>>(
            nullptr, 1, ffn_W1 + (size_t)b * 262144, ffn_W1, ffn_W1,
            ffn_b1 + b * 1024, -1, 6, 256, 1024, nullptr, nullptr, nullptr);
        // ffn2: h = h + t @ W2^T + b2 (K=1024)
        k_gemm_tc<EPI_BIAS | EPI_RES><<<dim3(4, 32, 1), 256>>>(
            nullptr, 6, ffn_W2 + (size_t)b * 262144, ffn_W2, ffn_W2,
            ffn_b2 + b * 256, 0, 0, 1024, 256, nullptr, nullptr, nullptr);
    }
    k_final<<<L, 96>>>(x_noisy, out_W, out_b, out);
}